// round 1
// baseline (speedup 1.0000x reference)
#include <cuda_runtime.h>
#include <math.h>

// ---------------------------------------------------------------------------
// GSSM fused kernel set.
// Inputs (metadata order):
//  0: x        (32,2048,512) f32
//  1: W_theta  (512,64)      2: b_theta (64)
//  3: W_lam    (512,1024)    4: b_lam   (1024)
//  5: W_delt   (512,1024)    6: b_delt  (1024)
//  7: W_inp    (512,1024)    8: b_inp   (1024)
//  9: W_par    (128,2)      10: b_par   (2)
// 11: W_add    (1024,1)     12: b_add   (1)
// Output: parity_logits (32,2) flattened [0..64) then add_pred (32,1) [64..96)
// ---------------------------------------------------------------------------

#define B_ 32
#define T_ 2048
#define DIN_ 512
#define M_ 1024
#define K_ 64

#define TT 64   // t-tile
#define MT 64   // m-tile
#define KC 32   // k-chunk
#define NTT (T_ / TT)   // 32 t-tiles
#define NMT (M_ / MT)   // 16 m-tiles
#define NKC (DIN_ / KC) // 16 k-chunks

// Scratch (static device memory -- no allocation allowed)
__device__ float g_A[B_ * NTT * M_];   // per (b, t-tile, m): product of alphas
__device__ float g_D[B_ * NTT * M_];   // per (b, t-tile, m): local drive term
__device__ float g_xs[B_ * DIN_];      // sum over T of x

// ---- packed fp32x2 helpers (Blackwell FFMA2 path) -------------------------
__device__ __forceinline__ unsigned long long pack2(float x) {
    unsigned long long r;
    asm("mov.b64 %0, {%1, %1};" : "=l"(r) : "f"(x));
    return r;
}
__device__ __forceinline__ void fma2(unsigned long long& c,
                                     unsigned long long a,
                                     unsigned long long b) {
    asm("fma.rn.f32x2 %0, %1, %2, %0;" : "+l"(c) : "l"(a), "l"(b));
}
__device__ __forceinline__ float lo32(unsigned long long u) {
    return __uint_as_float((unsigned)(u & 0xffffffffull));
}
__device__ __forceinline__ float hi32(unsigned long long u) {
    return __uint_as_float((unsigned)(u >> 32));
}

__device__ __forceinline__ float softplus_f(float z) {
    // matches jax.nn.softplus: log1p(exp(z)), numerically stable
    return fmaxf(z, 0.0f) + log1pf(expf(-fabsf(z)));
}

// ---------------------------------------------------------------------------
// Kernel A: xs[b,d] = sum_t x[b,t,d]   (fp64 accumulation)
// grid (4, 32), 128 threads
// ---------------------------------------------------------------------------
__global__ void xs_kernel(const float* __restrict__ x) {
    int b = blockIdx.y;
    int d = blockIdx.x * 128 + threadIdx.x;
    const float* xp = x + (size_t)b * T_ * DIN_ + d;
    double a0 = 0.0, a1 = 0.0, a2 = 0.0, a3 = 0.0;
    for (int t = 0; t < T_; t += 4) {
        a0 += (double)xp[(size_t)(t + 0) * DIN_];
        a1 += (double)xp[(size_t)(t + 1) * DIN_];
        a2 += (double)xp[(size_t)(t + 2) * DIN_];
        a3 += (double)xp[(size_t)(t + 3) * DIN_];
    }
    g_xs[b * DIN_ + d] = (float)((a0 + a1) + (a2 + a3));
}

// ---------------------------------------------------------------------------
// Kernel B: fused triple GEMM + softplus/exp + local scan over the t-tile.
// grid (NMT, NTT, B_) = (16, 32, 32), 256 threads.
// Each CTA: z = x_tile(64x512) @ {W_lam,W_delt,W_inp}(512x64) + bias,
// then alpha = exp(-softplus(zd)*softplus(zl)), drive = softplus(zd)*zi,
// reduced over the 64 t's into (A, D) per m column.
// ---------------------------------------------------------------------------
__global__ void __launch_bounds__(256, 2)
gssm_main_kernel(const float* __restrict__ x,
                 const float* __restrict__ W_lam, const float* __restrict__ b_lam,
                 const float* __restrict__ W_delt, const float* __restrict__ b_delt,
                 const float* __restrict__ W_inp, const float* __restrict__ b_inp) {
    const int mt = blockIdx.x;
    const int tt = blockIdx.y;
    const int b  = blockIdx.z;
    const int t0 = tt * TT;
    const int m0 = mt * MT;

    const int tid = threadIdx.x;
    const int tx = tid & 15;   // m sub-index (owns 4 consecutive m)
    const int ty = tid >> 4;   // t sub-index (owns 4 consecutive t)

    // smem: x tile stored [t][k] with row stride 36 (16B-aligned, pad vs conflicts)
    __shared__ __align__(16) float smx[TT * 36];        // 9216 B
    __shared__ __align__(16) float smw[3][KC * MT];     // 24576 B
    __shared__ float sA[16 * MT];                       // 4096 B
    __shared__ float sD[16 * MT];                       // 4096 B

    unsigned long long acc[3][4][2];
#pragma unroll
    for (int m3 = 0; m3 < 3; ++m3)
#pragma unroll
        for (int i = 0; i < 4; ++i) {
            acc[m3][i][0] = 0ull;
            acc[m3][i][1] = 0ull;
        }

    const float* Wp0 = W_lam;
    const float* Wp1 = W_delt;
    const float* Wp2 = W_inp;

    for (int ic = 0; ic < NKC; ++ic) {
        const int k0 = ic * KC;
        __syncthreads();
        // load x tile: 64 t x 32 k = 512 float4
        {
            int q = tid;           // 256 threads, 2 float4 each
#pragma unroll
            for (int r = 0; r < 2; ++r, q += 256) {
                int t = q >> 3;
                int kq = (q & 7) << 2;
                float4 v = *(const float4*)(x + ((size_t)b * T_ + t0 + t) * DIN_ + k0 + kq);
                *(float4*)&smx[t * 36 + kq] = v;
            }
        }
        // load 3 W tiles: 3 x (32 k x 64 m) = 1536 float4, 6 per thread
        {
            int q = tid;
#pragma unroll
            for (int r = 0; r < 6; ++r, q += 256) {
                int m3 = q >> 9;           // 0..2
                int p = q & 511;
                int k = p >> 4;
                int c4 = (p & 15) << 2;
                const float* Wp = (m3 == 0) ? Wp0 : ((m3 == 1) ? Wp1 : Wp2);
                float4 v = *(const float4*)(Wp + (size_t)(k0 + k) * M_ + m0 + c4);
                *(float4*)&smw[m3][k * MT + c4] = v;
            }
        }
        __syncthreads();

#pragma unroll 4
        for (int k = 0; k < KC; ++k) {
            unsigned long long a2[4];
#pragma unroll
            for (int i = 0; i < 4; ++i)
                a2[i] = pack2(smx[(ty * 4 + i) * 36 + k]);
#pragma unroll
            for (int m3 = 0; m3 < 3; ++m3) {
                ulonglong2 bb = *(const ulonglong2*)&smw[m3][k * MT + tx * 4];
#pragma unroll
                for (int i = 0; i < 4; ++i) {
                    fma2(acc[m3][i][0], a2[i], bb.x);
                    fma2(acc[m3][i][1], a2[i], bb.y);
                }
            }
        }
    }

    // ---- epilogue: bias, softplus, exp, local scan over this thread's 4 t's
    float4 bl4 = *(const float4*)&b_lam[m0 + tx * 4];
    float4 bd4 = *(const float4*)&b_delt[m0 + tx * 4];
    float4 bi4 = *(const float4*)&b_inp[m0 + tx * 4];
    const float bl[4] = {bl4.x, bl4.y, bl4.z, bl4.w};
    const float bd[4] = {bd4.x, bd4.y, bd4.z, bd4.w};
    const float bi[4] = {bi4.x, bi4.y, bi4.z, bi4.w};

    float Ath[4] = {1.f, 1.f, 1.f, 1.f};
    float Dth[4] = {0.f, 0.f, 0.f, 0.f};
#pragma unroll
    for (int i = 0; i < 4; ++i) {   // ascending t within this thread
#pragma unroll
        for (int jj = 0; jj < 4; ++jj) {
            unsigned long long ul = acc[0][i][jj >> 1];
            unsigned long long ud = acc[1][i][jj >> 1];
            unsigned long long ui = acc[2][i][jj >> 1];
            float zl = ((jj & 1) ? hi32(ul) : lo32(ul)) + bl[jj];
            float zd = ((jj & 1) ? hi32(ud) : lo32(ud)) + bd[jj];
            float zi = ((jj & 1) ? hi32(ui) : lo32(ui)) + bi[jj];
            float lam  = softplus_f(zl);
            float delt = softplus_f(zd);
            float alpha = expf(-delt * lam);
            float drive = delt * zi;
            Dth[jj] = Dth[jj] * alpha + drive;
            Ath[jj] = Ath[jj] * alpha;
        }
    }
#pragma unroll
    for (int jj = 0; jj < 4; ++jj) {
        sA[ty * MT + tx * 4 + jj] = Ath[jj];
        sD[ty * MT + tx * 4 + jj] = Dth[jj];
    }
    __syncthreads();

    if (tid < MT) {
        int m = tid;
        float At = 1.f, Dt = 0.f;
#pragma unroll
        for (int r = 0; r < 16; ++r) {   // ascending t
            float a = sA[r * MT + m];
            Dt = Dt * a + sD[r * MT + m];
            At *= a;
        }
        size_t idx = ((size_t)(b * NTT + tt)) * M_ + m0 + m;
        g_A[idx] = At;
        g_D[idx] = Dt;
    }
}

// ---------------------------------------------------------------------------
// Kernel C: combine 32 t-tiles per (b,m), then add_pred[b] = s . W_add + b_add
// grid 32 (per b), 1024 threads (per m)
// ---------------------------------------------------------------------------
__global__ void combine_kernel(const float* __restrict__ W_add,
                               const float* __restrict__ b_add,
                               float* __restrict__ out) {
    int b = blockIdx.x;
    int m = threadIdx.x;
    float s = 0.f;
#pragma unroll 8
    for (int tt = 0; tt < NTT; ++tt) {
        size_t idx = ((size_t)(b * NTT + tt)) * M_ + m;
        s = g_A[idx] * s + g_D[idx];
    }
    float v = s * W_add[m];
    // block reduce 1024 -> 1
    __shared__ float red[32];
    for (int off = 16; off > 0; off >>= 1)
        v += __shfl_down_sync(0xffffffffu, v, off);
    if ((m & 31) == 0) red[m >> 5] = v;
    __syncthreads();
    if (m < 32) {
        float w = red[m];
        for (int off = 16; off > 0; off >>= 1)
            w += __shfl_down_sync(0xffffffffu, w, off);
        if (m == 0) out[2 * B_ + b] = w + b_add[0];
    }
}

// ---------------------------------------------------------------------------
// Kernel P: parity path. ang = pi*(xs @ W_theta + T*b_theta) in fp64, then
// g = [cos, sin], logits = g @ W_par + b_par.
// grid 32 (per b), 64 threads (per k)
// ---------------------------------------------------------------------------
__global__ void parity_kernel(const float* __restrict__ W_theta,
                              const float* __restrict__ b_theta,
                              const float* __restrict__ W_par,
                              const float* __restrict__ b_par,
                              float* __restrict__ out) {
    int b = blockIdx.x;
    int k = threadIdx.x;
    double acc = 0.0;
    const float* xsb = &g_xs[b * DIN_];
    for (int d = 0; d < DIN_; ++d)
        acc += (double)xsb[d] * (double)W_theta[d * K_ + k];
    acc += (double)T_ * (double)b_theta[k];
    double ang = 3.14159265358979323846 * acc;
    double sn, cs;
    sincos(ang, &sn, &cs);
    __shared__ float g[2 * K_];
    g[k] = (float)cs;
    g[K_ + k] = (float)sn;
    __syncthreads();
    if (k < 2) {
        float l = b_par[k];
        for (int j = 0; j < 2 * K_; ++j)
            l += g[j] * W_par[j * 2 + k];
        out[b * 2 + k] = l;
    }
}

// ---------------------------------------------------------------------------
extern "C" void kernel_launch(void* const* d_in, const int* in_sizes, int n_in,
                              void* d_out, int out_size) {
    const float* x       = (const float*)d_in[0];
    const float* W_theta = (const float*)d_in[1];
    const float* b_theta = (const float*)d_in[2];
    const float* W_lam   = (const float*)d_in[3];
    const float* b_lam   = (const float*)d_in[4];
    const float* W_delt  = (const float*)d_in[5];
    const float* b_delt  = (const float*)d_in[6];
    const float* W_inp   = (const float*)d_in[7];
    const float* b_inp   = (const float*)d_in[8];
    const float* W_par   = (const float*)d_in[9];
    const float* b_par   = (const float*)d_in[10];
    const float* W_add   = (const float*)d_in[11];
    const float* b_add   = (const float*)d_in[12];
    float* out = (float*)d_out;

    // Parity branch prep: reduce x over T
    {
        dim3 g(DIN_ / 128, B_);
        xs_kernel<<<g, 128>>>(x);
    }
    // Main fused GEMM + local scan
    {
        dim3 g(NMT, NTT, B_);
        gssm_main_kernel<<<g, 256>>>(x, W_lam, b_lam, W_delt, b_delt, W_inp, b_inp);
    }
    // Parity head
    parity_kernel<<<B_, K_>>>(W_theta, b_theta, W_par, b_par, out);
    // Scan combine + add head
    combine_kernel<<<B_, M_>>>(W_add, b_add, out);
}

// round 3
// speedup vs baseline: 1.8769x; 1.8769x over previous
#include <cuda_runtime.h>
#include <cuda_bf16.h>
#include <math.h>
#include <stdint.h>

// ---------------------------------------------------------------------------
// GSSM — mma.sync (HMMA) bf16-split implementation.
// tcgen05 is NOT available: the harness compiles a compute_103 (non-'a') PTX
// target, which rejects all tcgen05/TMEM instructions. mma.sync m16n8k16 bf16
// + ldmatrix + cp.async are plain sm_80+ PTX and reach the tensor pipe.
//
// Inputs (metadata order):
//  0: x(32,2048,512) 1: W_theta(512,64) 2: b_theta(64)
//  3: W_lam(512,1024) 4: b_lam 5: W_delt 6: b_delt 7: W_inp 8: b_inp
//  9: W_par(128,2) 10: b_par(2) 11: W_add(1024,1) 12: b_add(1)
// Output: parity_logits (32,2) at [0,64), add_pred (32,1) at [64,96)
// ---------------------------------------------------------------------------

#define B_ 32
#define T_ 2048
#define DIN_ 512
#define M_ 1024
#define K_ 64

#define TB 128               // t rows per CTA
#define MB 64                // m cols per CTA
#define KC 32                // k per chunk
#define NKC (DIN_ / KC)      // 16 chunks
#define NTT2 (T_ / TB)       // 16 t-tiles per batch
#define NMB (M_ / MB)        // 16 m-tiles

// smem stage layout (bf16, padded rows of 40 elems = 80 B):
//   A: [2 split][128 rows][40]  = 20480 B
//   B: [6 w*s  ][ 64 rows][40]  = 30720 B
#define A_ROW_B 80
#define STAGE_A 20480
#define STAGE_BYTES 51200
#define NSTAGES 3
#define SMEM_BYTES (STAGE_BYTES * NSTAGES)   // 153600

// ---- static device scratch (no allocation allowed) ------------------------
__device__ __nv_bfloat16 g_xhi[(size_t)B_ * T_ * DIN_];
__device__ __nv_bfloat16 g_xlo[(size_t)B_ * T_ * DIN_];
__device__ __nv_bfloat16 g_wthi[3u * M_ * DIN_];   // [w][m][k] K-major
__device__ __nv_bfloat16 g_wtlo[3u * M_ * DIN_];
__device__ float g_A[B_ * NTT2 * M_];
__device__ float g_D[B_ * NTT2 * M_];
__device__ float g_xs[B_ * DIN_];

// ---- helpers ---------------------------------------------------------------
__device__ __forceinline__ uint32_t smem_u32(const void* p) {
    uint32_t a;
    asm("{ .reg .u64 t; cvta.to.shared.u64 t, %1; cvt.u32.u64 %0, t; }"
        : "=r"(a) : "l"(p));
    return a;
}

__device__ __forceinline__ void cp_async16(uint32_t dst, const void* src) {
    asm volatile("cp.async.cg.shared.global [%0], [%1], 16;"
                 :: "r"(dst), "l"(src) : "memory");
}

__device__ __forceinline__ void ldsm_x4(uint32_t* r, uint32_t addr) {
    asm volatile("ldmatrix.sync.aligned.m8n8.x4.shared.b16 {%0,%1,%2,%3}, [%4];"
                 : "=r"(r[0]), "=r"(r[1]), "=r"(r[2]), "=r"(r[3]) : "r"(addr));
}

__device__ __forceinline__ void mma16816(float* d, const uint32_t* a,
                                         const uint32_t* b) {
    asm volatile(
        "mma.sync.aligned.m16n8k16.row.col.f32.bf16.bf16.f32 "
        "{%0,%1,%2,%3}, {%4,%5,%6,%7}, {%8,%9}, {%0,%1,%2,%3};"
        : "+f"(d[0]), "+f"(d[1]), "+f"(d[2]), "+f"(d[3])
        : "r"(a[0]), "r"(a[1]), "r"(a[2]), "r"(a[3]), "r"(b[0]), "r"(b[1]));
}

__device__ __forceinline__ float softplus_f(float z) {
    return fmaxf(z, 0.0f) + log1pf(expf(-fabsf(z)));
}

// ---------------------------------------------------------------------------
// Prep 1: split x -> bf16 hi/lo
// ---------------------------------------------------------------------------
__global__ void xsplit_kernel(const float* __restrict__ x) {
    size_t i = ((size_t)blockIdx.x * 256 + threadIdx.x) * 8;
    float4 v0 = *(const float4*)(x + i);
    float4 v1 = *(const float4*)(x + i + 4);
    float f[8] = {v0.x, v0.y, v0.z, v0.w, v1.x, v1.y, v1.z, v1.w};
    __align__(16) __nv_bfloat16 h[8];
    __align__(16) __nv_bfloat16 l[8];
#pragma unroll
    for (int j = 0; j < 8; ++j) {
        h[j] = __float2bfloat16(f[j]);
        l[j] = __float2bfloat16(f[j] - __bfloat162float(h[j]));
    }
    *(uint4*)&g_xhi[i] = *(const uint4*)h;
    *(uint4*)&g_xlo[i] = *(const uint4*)l;
}

// ---------------------------------------------------------------------------
// Prep 2: transpose + split W (512x1024 f32) -> [w][m][k] bf16 hi/lo
// ---------------------------------------------------------------------------
__global__ void wtsplit_kernel(const float* __restrict__ Wl,
                               const float* __restrict__ Wd,
                               const float* __restrict__ Wi) {
    __shared__ float tile[32][33];
    const int w = blockIdx.z;
    const float* W = (w == 0) ? Wl : ((w == 1) ? Wd : Wi);
    const int m0 = blockIdx.x * 32;
    const int k0 = blockIdx.y * 32;
    const int tx = threadIdx.x & 31;
    const int ty = threadIdx.x >> 5;
#pragma unroll
    for (int r = 0; r < 4; ++r)
        tile[ty + 8 * r][tx] = W[(size_t)(k0 + ty + 8 * r) * M_ + m0 + tx];
    __syncthreads();
#pragma unroll
    for (int r = 0; r < 4; ++r) {
        int m = ty + 8 * r;
        int k = tx;
        float v = tile[k][m];
        __nv_bfloat16 h = __float2bfloat16(v);
        __nv_bfloat16 lo = __float2bfloat16(v - __bfloat162float(h));
        size_t o = ((size_t)w * M_ + m0 + m) * DIN_ + k0 + k;
        g_wthi[o] = h;
        g_wtlo[o] = lo;
    }
}

// ---------------------------------------------------------------------------
// Kernel A: xs[b,d] = sum_t x[b,t,d]   (fp64 accumulation; parity branch)
// ---------------------------------------------------------------------------
__global__ void xs_kernel(const float* __restrict__ x) {
    int b = blockIdx.y;
    int d = blockIdx.x * 128 + threadIdx.x;
    const float* xp = x + (size_t)b * T_ * DIN_ + d;
    double a0 = 0.0, a1 = 0.0, a2 = 0.0, a3 = 0.0;
    for (int t = 0; t < T_; t += 4) {
        a0 += (double)xp[(size_t)(t + 0) * DIN_];
        a1 += (double)xp[(size_t)(t + 1) * DIN_];
        a2 += (double)xp[(size_t)(t + 2) * DIN_];
        a3 += (double)xp[(size_t)(t + 3) * DIN_];
    }
    g_xs[b * DIN_ + d] = (float)((a0 + a1) + (a2 + a3));
}

// ---------------------------------------------------------------------------
// Main kernel: HMMA split-bf16 triple-GEMM + fused softplus/exp + t-scan.
// grid (16 m-tiles, 512 bt-tiles), 256 threads (8 warps: 4 t x 2 m).
// ---------------------------------------------------------------------------
__global__ void __launch_bounds__(256, 1)
gssm_mma_kernel(const float* __restrict__ b_lam,
                const float* __restrict__ b_delt,
                const float* __restrict__ b_inp) {
    extern __shared__ __align__(128) char smem[];
    const uint32_t sb = smem_u32(smem);
    const int tid = threadIdx.x;
    const int lane = tid & 31;
    const int wid = tid >> 5;
    const int wt = wid & 3;        // t-quadrant: rows wt*32..+31
    const int wm = wid >> 2;       // m-half:   cols wm*32..+31
    const int mb = blockIdx.x;
    const int tb = blockIdx.y;     // b*16 + tt
    const int m0 = mb * MB;
    const int r0 = tb * TB;

    float acc[3][2][4][4];
#pragma unroll
    for (int w = 0; w < 3; ++w)
#pragma unroll
        for (int ts = 0; ts < 2; ++ts)
#pragma unroll
            for (int nt = 0; nt < 4; ++nt)
#pragma unroll
                for (int f = 0; f < 4; ++f) acc[w][ts][nt][f] = 0.f;

    auto issue_load = [&](int ic, int stg) {
        const int kc0 = ic * KC;
        const uint32_t sbase = sb + stg * STAGE_BYTES;
        // A: 2 splits x 128 rows x 32k bf16 = 1024 x 16B
#pragma unroll
        for (int q = 0; q < 4; ++q) {
            int idx = q * 256 + tid;
            int split = idx >> 9;
            int r = (idx >> 2) & 127;
            int v = idx & 3;
            const __nv_bfloat16* g =
                (split ? g_xlo : g_xhi) + (size_t)(r0 + r) * DIN_ + kc0 + v * 8;
            cp_async16(sbase + split * 10240 + r * A_ROW_B + v * 16, g);
        }
        // B: 6 (w,s) x 64 rows x 32k = 1536 x 16B
#pragma unroll
        for (int q = 0; q < 6; ++q) {
            int idx = q * 256 + tid;
            int ws = idx >> 8;
            int w = ws >> 1, s = ws & 1;
            int n = (idx >> 2) & 63;
            int v = idx & 3;
            const __nv_bfloat16* g =
                (s ? g_wtlo : g_wthi) + ((size_t)w * M_ + m0 + n) * DIN_ + kc0 + v * 8;
            cp_async16(sbase + STAGE_A + ws * 5120 + n * A_ROW_B + v * 16, g);
        }
        asm volatile("cp.async.commit_group;" ::: "memory");
    };

    auto compute = [&](int stg) {
        const uint32_t aB = sb + stg * STAGE_BYTES;
        const uint32_t bB = aB + STAGE_A;
        const int rsub = (lane & 7) + 8 * ((lane >> 3) & 1);
        const int ksub = 8 * (lane >> 4);
#pragma unroll
        for (int kk = 0; kk < 2; ++kk) {
            const int kcol = kk * 16 + ksub;
            uint32_t ah[2][4], al[2][4];
#pragma unroll
            for (int ts = 0; ts < 2; ++ts) {
                int row = wt * 32 + ts * 16 + rsub;
                ldsm_x4(ah[ts], aB + 0 + row * A_ROW_B + kcol * 2);
                ldsm_x4(al[ts], aB + 10240 + row * A_ROW_B + kcol * 2);
            }
            uint32_t bf[6][4][2];
#pragma unroll
            for (int ws = 0; ws < 6; ++ws) {
#pragma unroll
                for (int p = 0; p < 2; ++p) {
                    uint32_t r4[4];
                    int nrow = wm * 32 + p * 16 + rsub;
                    ldsm_x4(r4, bB + ws * 5120 + nrow * A_ROW_B + kcol * 2);
                    bf[ws][p * 2 + 0][0] = r4[0];
                    bf[ws][p * 2 + 1][0] = r4[1];
                    bf[ws][p * 2 + 0][1] = r4[2];
                    bf[ws][p * 2 + 1][1] = r4[3];
                }
            }
#pragma unroll
            for (int w = 0; w < 3; ++w)
#pragma unroll
                for (int ts = 0; ts < 2; ++ts)
#pragma unroll
                    for (int nt = 0; nt < 4; ++nt) {
                        mma16816(acc[w][ts][nt], ah[ts], bf[2 * w + 0][nt]);
                        mma16816(acc[w][ts][nt], al[ts], bf[2 * w + 0][nt]);
                        mma16816(acc[w][ts][nt], ah[ts], bf[2 * w + 1][nt]);
                    }
        }
    };

    issue_load(0, 0);
    issue_load(1, 1);
    for (int ic = 0; ic < NKC; ++ic) {
        if (ic + 2 < NKC) issue_load(ic + 2, (ic + 2) % NSTAGES);
        if (ic < NKC - 2)
            asm volatile("cp.async.wait_group 2;" ::: "memory");
        else if (ic == NKC - 2)
            asm volatile("cp.async.wait_group 1;" ::: "memory");
        else
            asm volatile("cp.async.wait_group 0;" ::: "memory");
        __syncthreads();
        compute(ic % NSTAGES);
        __syncthreads();
    }

    // ---- fused epilogue: bias + softplus + exp, then t-scan ----
    float* salpha = (float*)smem;                      // [128][66]
    float* sdrive = (float*)(smem + 33792);            // [128][66]
    float* sAp = (float*)(smem + 131072);              // [4][64]
    float* sDp = (float*)(smem + 131072 + 1024);       // [4][64]

#pragma unroll
    for (int ts = 0; ts < 2; ++ts) {
#pragma unroll
        for (int nt = 0; nt < 4; ++nt) {
            const int mloc = wm * 32 + nt * 8 + 2 * (lane & 3);
            const float2 bl = *(const float2*)&b_lam[m0 + mloc];
            const float2 bd = *(const float2*)&b_delt[m0 + mloc];
            const float2 bi = *(const float2*)&b_inp[m0 + mloc];
#pragma unroll
            for (int h = 0; h < 2; ++h) {
                const int t = wt * 32 + ts * 16 + h * 8 + (lane >> 2);
#pragma unroll
                for (int c = 0; c < 2; ++c) {
                    float zl = acc[0][ts][nt][h * 2 + c] + (c ? bl.y : bl.x);
                    float zd = acc[1][ts][nt][h * 2 + c] + (c ? bd.y : bd.x);
                    float zi = acc[2][ts][nt][h * 2 + c] + (c ? bi.y : bi.x);
                    float lamv = softplus_f(zl);
                    float dlv = softplus_f(zd);
                    salpha[t * 66 + mloc + c] = expf(-dlv * lamv);
                    sdrive[t * 66 + mloc + c] = dlv * zi;
                }
            }
        }
    }
    __syncthreads();
    {
        const int m = tid & 63;
        const int ty = tid >> 6;
        float A = 1.f, D = 0.f;
#pragma unroll 8
        for (int r = 0; r < 32; ++r) {
            int t = ty * 32 + r;
            float a = salpha[t * 66 + m];
            D = a * D + sdrive[t * 66 + m];
            A *= a;
        }
        sAp[ty * 64 + m] = A;
        sDp[ty * 64 + m] = D;
    }
    __syncthreads();
    if (tid < 64) {
        float A = 1.f, D = 0.f;
#pragma unroll
        for (int r = 0; r < 4; ++r) {
            float a = sAp[r * 64 + tid];
            D = a * D + sDp[r * 64 + tid];
            A *= a;
        }
        size_t o = (size_t)tb * M_ + m0 + tid;
        g_A[o] = A;
        g_D[o] = D;
    }
}

// ---------------------------------------------------------------------------
// Kernel C: combine 16 t-tiles per (b,m), then add_pred[b] = s . W_add + b_add
// ---------------------------------------------------------------------------
__global__ void combine_kernel(const float* __restrict__ W_add,
                               const float* __restrict__ b_add,
                               float* __restrict__ out) {
    int b = blockIdx.x;
    int m = threadIdx.x;
    float s = 0.f;
#pragma unroll
    for (int tt = 0; tt < NTT2; ++tt) {
        size_t idx = ((size_t)(b * NTT2 + tt)) * M_ + m;
        s = g_A[idx] * s + g_D[idx];
    }
    float v = s * W_add[m];
    __shared__ float red[32];
    for (int off = 16; off > 0; off >>= 1)
        v += __shfl_down_sync(0xffffffffu, v, off);
    if ((m & 31) == 0) red[m >> 5] = v;
    __syncthreads();
    if (m < 32) {
        float w = red[m];
        for (int off = 16; off > 0; off >>= 1)
            w += __shfl_down_sync(0xffffffffu, w, off);
        if (m == 0) out[2 * B_ + b] = w + b_add[0];
    }
}

// ---------------------------------------------------------------------------
// Kernel P: parity path (fp64 angle accumulation)
// ---------------------------------------------------------------------------
__global__ void parity_kernel(const float* __restrict__ W_theta,
                              const float* __restrict__ b_theta,
                              const float* __restrict__ W_par,
                              const float* __restrict__ b_par,
                              float* __restrict__ out) {
    int b = blockIdx.x;
    int k = threadIdx.x;
    double acc = 0.0;
    const float* xsb = &g_xs[b * DIN_];
    for (int d = 0; d < DIN_; ++d)
        acc += (double)xsb[d] * (double)W_theta[d * K_ + k];
    acc += (double)T_ * (double)b_theta[k];
    double ang = 3.14159265358979323846 * acc;
    double sn, cs;
    sincos(ang, &sn, &cs);
    __shared__ float g[2 * K_];
    g[k] = (float)cs;
    g[K_ + k] = (float)sn;
    __syncthreads();
    if (k < 2) {
        float l = b_par[k];
        for (int j = 0; j < 2 * K_; ++j)
            l += g[j] * W_par[j * 2 + k];
        out[b * 2 + k] = l;
    }
}

// ---------------------------------------------------------------------------
extern "C" void kernel_launch(void* const* d_in, const int* in_sizes, int n_in,
                              void* d_out, int out_size) {
    const float* x       = (const float*)d_in[0];
    const float* W_theta = (const float*)d_in[1];
    const float* b_theta = (const float*)d_in[2];
    const float* W_lam   = (const float*)d_in[3];
    const float* b_lam   = (const float*)d_in[4];
    const float* W_delt  = (const float*)d_in[5];
    const float* b_delt  = (const float*)d_in[6];
    const float* W_inp   = (const float*)d_in[7];
    const float* b_inp   = (const float*)d_in[8];
    const float* W_par   = (const float*)d_in[9];
    const float* b_par   = (const float*)d_in[10];
    const float* W_add   = (const float*)d_in[11];
    const float* b_add   = (const float*)d_in[12];
    float* out = (float*)d_out;

    static int smem_set = 0;
    if (!smem_set) {
        cudaFuncSetAttribute(gssm_mma_kernel,
                             cudaFuncAttributeMaxDynamicSharedMemorySize,
                             SMEM_BYTES);
        smem_set = 1;
    }

    // Prep: split/convert inputs
    xsplit_kernel<<<((size_t)B_ * T_ * DIN_) / (256 * 8), 256>>>(x);
    wtsplit_kernel<<<dim3(32, 16, 3), 256>>>(W_lam, W_delt, W_inp);
    xs_kernel<<<dim3(DIN_ / 128, B_), 128>>>(x);

    // Main fused tensor-core GEMM + scan-reduce
    gssm_mma_kernel<<<dim3(NMB, B_ * NTT2), 256, SMEM_BYTES>>>(b_lam, b_delt, b_inp);

    // Heads
    parity_kernel<<<B_, K_>>>(W_theta, b_theta, W_par, b_par, out);
    combine_kernel<<<B_, M_>>>(W_add, b_add, out);
}

// round 4
// speedup vs baseline: 1.8993x; 1.0120x over previous
#include <cuda_runtime.h>
#include <cuda_bf16.h>
#include <math.h>
#include <stdint.h>

// ---------------------------------------------------------------------------
// GSSM — mma.sync (HMMA) bf16-split implementation, round 4:
//  - single __syncthreads per k-chunk (reordered 3-stage cp.async pipeline)
//  - all cp.async / ldmatrix address math hoisted out of the main loop
//  - product-outer MMA ordering (no back-to-back RAW on accumulators)
//
// Inputs (metadata order):
//  0: x(32,2048,512) 1: W_theta(512,64) 2: b_theta(64)
//  3: W_lam(512,1024) 4: b_lam 5: W_delt 6: b_delt 7: W_inp 8: b_inp
//  9: W_par(128,2) 10: b_par(2) 11: W_add(1024,1) 12: b_add(1)
// Output: parity_logits (32,2) at [0,64), add_pred (32,1) at [64,96)
// ---------------------------------------------------------------------------

#define B_ 32
#define T_ 2048
#define DIN_ 512
#define M_ 1024
#define K_ 64

#define TB 128               // t rows per CTA
#define MB 64                // m cols per CTA
#define KC 32                // k per chunk
#define NKC (DIN_ / KC)      // 16 chunks
#define NTT2 (T_ / TB)       // 16 t-tiles per batch
#define NMB (M_ / MB)        // 16 m-tiles

// smem stage layout (bf16, padded rows of 40 elems = 80 B):
//   A: [2 split][128 rows][40]  = 20480 B
//   B: [6 w*s  ][ 64 rows][40]  = 30720 B
#define A_ROW_B 80
#define STAGE_A 20480
#define STAGE_BYTES 51200
#define NSTAGES 3
#define SMEM_BYTES (STAGE_BYTES * NSTAGES)   // 153600

// ---- static device scratch (no allocation allowed) ------------------------
__device__ __nv_bfloat16 g_xhi[(size_t)B_ * T_ * DIN_];
__device__ __nv_bfloat16 g_xlo[(size_t)B_ * T_ * DIN_];
__device__ __nv_bfloat16 g_wthi[3u * M_ * DIN_];   // [w][m][k] K-major
__device__ __nv_bfloat16 g_wtlo[3u * M_ * DIN_];
__device__ float g_A[B_ * NTT2 * M_];
__device__ float g_D[B_ * NTT2 * M_];
__device__ float g_xs[B_ * DIN_];

// ---- helpers ---------------------------------------------------------------
__device__ __forceinline__ uint32_t smem_u32(const void* p) {
    uint32_t a;
    asm("{ .reg .u64 t; cvta.to.shared.u64 t, %1; cvt.u32.u64 %0, t; }"
        : "=r"(a) : "l"(p));
    return a;
}

__device__ __forceinline__ void cp_async16(uint32_t dst, const void* src) {
    asm volatile("cp.async.cg.shared.global [%0], [%1], 16;"
                 :: "r"(dst), "l"(src) : "memory");
}

__device__ __forceinline__ void ldsm_x4(uint32_t* r, uint32_t addr) {
    asm volatile("ldmatrix.sync.aligned.m8n8.x4.shared.b16 {%0,%1,%2,%3}, [%4];"
                 : "=r"(r[0]), "=r"(r[1]), "=r"(r[2]), "=r"(r[3]) : "r"(addr));
}

__device__ __forceinline__ void mma16816(float* d, const uint32_t* a,
                                         const uint32_t* b) {
    asm volatile(
        "mma.sync.aligned.m16n8k16.row.col.f32.bf16.bf16.f32 "
        "{%0,%1,%2,%3}, {%4,%5,%6,%7}, {%8,%9}, {%0,%1,%2,%3};"
        : "+f"(d[0]), "+f"(d[1]), "+f"(d[2]), "+f"(d[3])
        : "r"(a[0]), "r"(a[1]), "r"(a[2]), "r"(a[3]), "r"(b[0]), "r"(b[1]));
}

__device__ __forceinline__ float softplus_f(float z) {
    return fmaxf(z, 0.0f) + log1pf(expf(-fabsf(z)));
}

// ---------------------------------------------------------------------------
// Prep 1: split x -> bf16 hi/lo
// ---------------------------------------------------------------------------
__global__ void xsplit_kernel(const float* __restrict__ x) {
    size_t i = ((size_t)blockIdx.x * 256 + threadIdx.x) * 8;
    float4 v0 = *(const float4*)(x + i);
    float4 v1 = *(const float4*)(x + i + 4);
    float f[8] = {v0.x, v0.y, v0.z, v0.w, v1.x, v1.y, v1.z, v1.w};
    __align__(16) __nv_bfloat16 h[8];
    __align__(16) __nv_bfloat16 l[8];
#pragma unroll
    for (int j = 0; j < 8; ++j) {
        h[j] = __float2bfloat16(f[j]);
        l[j] = __float2bfloat16(f[j] - __bfloat162float(h[j]));
    }
    *(uint4*)&g_xhi[i] = *(const uint4*)h;
    *(uint4*)&g_xlo[i] = *(const uint4*)l;
}

// ---------------------------------------------------------------------------
// Prep 2: transpose + split W (512x1024 f32) -> [w][m][k] bf16 hi/lo
// ---------------------------------------------------------------------------
__global__ void wtsplit_kernel(const float* __restrict__ Wl,
                               const float* __restrict__ Wd,
                               const float* __restrict__ Wi) {
    __shared__ float tile[32][33];
    const int w = blockIdx.z;
    const float* W = (w == 0) ? Wl : ((w == 1) ? Wd : Wi);
    const int m0 = blockIdx.x * 32;
    const int k0 = blockIdx.y * 32;
    const int tx = threadIdx.x & 31;
    const int ty = threadIdx.x >> 5;
#pragma unroll
    for (int r = 0; r < 4; ++r)
        tile[ty + 8 * r][tx] = W[(size_t)(k0 + ty + 8 * r) * M_ + m0 + tx];
    __syncthreads();
#pragma unroll
    for (int r = 0; r < 4; ++r) {
        int m = ty + 8 * r;
        int k = tx;
        float v = tile[k][m];
        __nv_bfloat16 h = __float2bfloat16(v);
        __nv_bfloat16 lo = __float2bfloat16(v - __bfloat162float(h));
        size_t o = ((size_t)w * M_ + m0 + m) * DIN_ + k0 + k;
        g_wthi[o] = h;
        g_wtlo[o] = lo;
    }
}

// ---------------------------------------------------------------------------
// Kernel A: xs[b,d] = sum_t x[b,t,d]   (fp64 accumulation; parity branch)
// ---------------------------------------------------------------------------
__global__ void xs_kernel(const float* __restrict__ x) {
    int b = blockIdx.y;
    int d = blockIdx.x * 128 + threadIdx.x;
    const float* xp = x + (size_t)b * T_ * DIN_ + d;
    double a0 = 0.0, a1 = 0.0, a2 = 0.0, a3 = 0.0;
    for (int t = 0; t < T_; t += 4) {
        a0 += (double)xp[(size_t)(t + 0) * DIN_];
        a1 += (double)xp[(size_t)(t + 1) * DIN_];
        a2 += (double)xp[(size_t)(t + 2) * DIN_];
        a3 += (double)xp[(size_t)(t + 3) * DIN_];
    }
    g_xs[b * DIN_ + d] = (float)((a0 + a1) + (a2 + a3));
}

// ---------------------------------------------------------------------------
// Main kernel: HMMA split-bf16 triple-GEMM + fused softplus/exp + t-scan.
// grid (16 m-tiles, 512 bt-tiles), 256 threads (8 warps: 4 t x 2 m).
// ---------------------------------------------------------------------------
__global__ void __launch_bounds__(256, 1)
gssm_mma_kernel(const float* __restrict__ b_lam,
                const float* __restrict__ b_delt,
                const float* __restrict__ b_inp) {
    extern __shared__ __align__(128) char smem[];
    const uint32_t sb = smem_u32(smem);
    const int tid = threadIdx.x;
    const int lane = tid & 31;
    const int wid = tid >> 5;
    const int wt = wid & 3;        // t-quadrant: rows wt*32..+31
    const int wm = wid >> 2;       // m-half:   cols wm*32..+31
    const int mb = blockIdx.x;
    const int tb = blockIdx.y;     // b*16 + tt
    const int m0 = mb * MB;
    const int r0 = tb * TB;

    // ---- hoisted cp.async source pointers / dest offsets -------------------
    const __nv_bfloat16* srcA[4];
    uint32_t dstA[4];
#pragma unroll
    for (int q = 0; q < 4; ++q) {
        int idx = q * 256 + tid;
        int split = idx >> 9;
        int r = (idx >> 2) & 127;
        int v = idx & 3;
        srcA[q] = (split ? g_xlo : g_xhi) + (size_t)(r0 + r) * DIN_ + v * 8;
        dstA[q] = sb + split * 10240 + r * A_ROW_B + v * 16;
    }
    const __nv_bfloat16* srcB[6];
    uint32_t dstB[6];
#pragma unroll
    for (int q = 0; q < 6; ++q) {
        int idx = q * 256 + tid;
        int ws = idx >> 8;
        int w = ws >> 1, s = ws & 1;
        int n = (idx >> 2) & 63;
        int v = idx & 3;
        srcB[q] = (s ? g_wtlo : g_wthi) + ((size_t)w * M_ + m0 + n) * DIN_ + v * 8;
        dstB[q] = sb + STAGE_A + ws * 5120 + n * A_ROW_B + v * 16;
    }

    // ---- hoisted ldmatrix row offsets --------------------------------------
    const int rsub = (lane & 7) + 8 * ((lane >> 3) & 1);
    const int ksub2 = 16 * (lane >> 4);           // ksub * 2 bytes
    uint32_t aRow[2], bRow[2];
#pragma unroll
    for (int ts = 0; ts < 2; ++ts)
        aRow[ts] = (uint32_t)((wt * 32 + ts * 16 + rsub) * A_ROW_B) + ksub2;
#pragma unroll
    for (int p = 0; p < 2; ++p)
        bRow[p] = (uint32_t)(STAGE_A + (wm * 32 + p * 16 + rsub) * A_ROW_B) + ksub2;

    float acc[3][2][4][4];
#pragma unroll
    for (int w = 0; w < 3; ++w)
#pragma unroll
        for (int ts = 0; ts < 2; ++ts)
#pragma unroll
            for (int nt = 0; nt < 4; ++nt)
#pragma unroll
                for (int f = 0; f < 4; ++f) acc[w][ts][nt][f] = 0.f;

    auto issue_load = [&](int ic, int stg) {
        const uint32_t so = stg * STAGE_BYTES;
        const size_t ko = (size_t)ic * KC;
#pragma unroll
        for (int q = 0; q < 4; ++q) cp_async16(dstA[q] + so, srcA[q] + ko);
#pragma unroll
        for (int q = 0; q < 6; ++q) cp_async16(dstB[q] + so, srcB[q] + ko);
        asm volatile("cp.async.commit_group;" ::: "memory");
    };

    auto compute = [&](int stg) {
        const uint32_t base = sb + stg * STAGE_BYTES;
#pragma unroll
        for (int kk = 0; kk < 2; ++kk) {
            const uint32_t kb = base + kk * 32;
            uint32_t ah[2][4], al[2][4];
#pragma unroll
            for (int ts = 0; ts < 2; ++ts) {
                ldsm_x4(ah[ts], kb + aRow[ts]);
                ldsm_x4(al[ts], kb + 10240 + aRow[ts]);
            }
            uint32_t bf[6][4][2];
#pragma unroll
            for (int ws = 0; ws < 6; ++ws) {
#pragma unroll
                for (int p = 0; p < 2; ++p) {
                    uint32_t r4[4];
                    ldsm_x4(r4, kb + ws * 5120 + bRow[p]);
                    bf[ws][p * 2 + 0][0] = r4[0];
                    bf[ws][p * 2 + 1][0] = r4[1];
                    bf[ws][p * 2 + 0][1] = r4[2];
                    bf[ws][p * 2 + 1][1] = r4[3];
                }
            }
            // product-outer ordering: 24 independent MMAs between RAW reuses
#pragma unroll
            for (int pr = 0; pr < 3; ++pr) {
#pragma unroll
                for (int w = 0; w < 3; ++w)
#pragma unroll
                    for (int ts = 0; ts < 2; ++ts)
#pragma unroll
                        for (int nt = 0; nt < 4; ++nt) {
                            const uint32_t* af = (pr == 1) ? al[ts] : ah[ts];
                            const uint32_t* bb = bf[2 * w + (pr == 2 ? 1 : 0)][nt];
                            mma16816(acc[w][ts][nt], af, bb);
                        }
            }
        }
    };

    issue_load(0, 0);
    issue_load(1, 1);
#pragma unroll 1
    for (int ic = 0; ic < NKC; ++ic) {
        if (ic < NKC - 1)
            asm volatile("cp.async.wait_group 1;" ::: "memory");
        else
            asm volatile("cp.async.wait_group 0;" ::: "memory");
        __syncthreads();
        if (ic + 2 < NKC) issue_load(ic + 2, (ic + 2) % NSTAGES);
        compute(ic % NSTAGES);
    }
    __syncthreads();   // all compute done before smem reuse by epilogue

    // ---- fused epilogue: bias + softplus + exp, then t-scan ----
    float* salpha = (float*)smem;                      // [128][66]
    float* sdrive = (float*)(smem + 33792);            // [128][66]
    float* sAp = (float*)(smem + 131072);              // [4][64]
    float* sDp = (float*)(smem + 131072 + 1024);       // [4][64]

#pragma unroll
    for (int ts = 0; ts < 2; ++ts) {
#pragma unroll
        for (int nt = 0; nt < 4; ++nt) {
            const int mloc = wm * 32 + nt * 8 + 2 * (lane & 3);
            const float2 bl = *(const float2*)&b_lam[m0 + mloc];
            const float2 bd = *(const float2*)&b_delt[m0 + mloc];
            const float2 bi = *(const float2*)&b_inp[m0 + mloc];
#pragma unroll
            for (int h = 0; h < 2; ++h) {
                const int t = wt * 32 + ts * 16 + h * 8 + (lane >> 2);
#pragma unroll
                for (int c = 0; c < 2; ++c) {
                    float zl = acc[0][ts][nt][h * 2 + c] + (c ? bl.y : bl.x);
                    float zd = acc[1][ts][nt][h * 2 + c] + (c ? bd.y : bd.x);
                    float zi = acc[2][ts][nt][h * 2 + c] + (c ? bi.y : bi.x);
                    float lamv = softplus_f(zl);
                    float dlv = softplus_f(zd);
                    salpha[t * 66 + mloc + c] = expf(-dlv * lamv);
                    sdrive[t * 66 + mloc + c] = dlv * zi;
                }
            }
        }
    }
    __syncthreads();
    {
        const int m = tid & 63;
        const int ty = tid >> 6;
        float A = 1.f, D = 0.f;
#pragma unroll 8
        for (int r = 0; r < 32; ++r) {
            int t = ty * 32 + r;
            float a = salpha[t * 66 + m];
            D = a * D + sdrive[t * 66 + m];
            A *= a;
        }
        sAp[ty * 64 + m] = A;
        sDp[ty * 64 + m] = D;
    }
    __syncthreads();
    if (tid < 64) {
        float A = 1.f, D = 0.f;
#pragma unroll
        for (int r = 0; r < 4; ++r) {
            float a = sAp[r * 64 + tid];
            D = a * D + sDp[r * 64 + tid];
            A *= a;
        }
        size_t o = (size_t)tb * M_ + m0 + tid;
        g_A[o] = A;
        g_D[o] = D;
    }
}

// ---------------------------------------------------------------------------
// Kernel C: combine 16 t-tiles per (b,m), then add_pred[b] = s . W_add + b_add
// ---------------------------------------------------------------------------
__global__ void combine_kernel(const float* __restrict__ W_add,
                               const float* __restrict__ b_add,
                               float* __restrict__ out) {
    int b = blockIdx.x;
    int m = threadIdx.x;
    float s = 0.f;
#pragma unroll
    for (int tt = 0; tt < NTT2; ++tt) {
        size_t idx = ((size_t)(b * NTT2 + tt)) * M_ + m;
        s = g_A[idx] * s + g_D[idx];
    }
    float v = s * W_add[m];
    __shared__ float red[32];
    for (int off = 16; off > 0; off >>= 1)
        v += __shfl_down_sync(0xffffffffu, v, off);
    if ((m & 31) == 0) red[m >> 5] = v;
    __syncthreads();
    if (m < 32) {
        float w = red[m];
        for (int off = 16; off > 0; off >>= 1)
            w += __shfl_down_sync(0xffffffffu, w, off);
        if (m == 0) out[2 * B_ + b] = w + b_add[0];
    }
}

// ---------------------------------------------------------------------------
// Kernel P: parity path (fp64 angle accumulation)
// ---------------------------------------------------------------------------
__global__ void parity_kernel(const float* __restrict__ W_theta,
                              const float* __restrict__ b_theta,
                              const float* __restrict__ W_par,
                              const float* __restrict__ b_par,
                              float* __restrict__ out) {
    int b = blockIdx.x;
    int k = threadIdx.x;
    double acc = 0.0;
    const float* xsb = &g_xs[b * DIN_];
    for (int d = 0; d < DIN_; ++d)
        acc += (double)xsb[d] * (double)W_theta[d * K_ + k];
    acc += (double)T_ * (double)b_theta[k];
    double ang = 3.14159265358979323846 * acc;
    double sn, cs;
    sincos(ang, &sn, &cs);
    __shared__ float g[2 * K_];
    g[k] = (float)cs;
    g[K_ + k] = (float)sn;
    __syncthreads();
    if (k < 2) {
        float l = b_par[k];
        for (int j = 0; j < 2 * K_; ++j)
            l += g[j] * W_par[j * 2 + k];
        out[b * 2 + k] = l;
    }
}

// ---------------------------------------------------------------------------
extern "C" void kernel_launch(void* const* d_in, const int* in_sizes, int n_in,
                              void* d_out, int out_size) {
    const float* x       = (const float*)d_in[0];
    const float* W_theta = (const float*)d_in[1];
    const float* b_theta = (const float*)d_in[2];
    const float* W_lam   = (const float*)d_in[3];
    const float* b_lam   = (const float*)d_in[4];
    const float* W_delt  = (const float*)d_in[5];
    const float* b_delt  = (const float*)d_in[6];
    const float* W_inp   = (const float*)d_in[7];
    const float* b_inp   = (const float*)d_in[8];
    const float* W_par   = (const float*)d_in[9];
    const float* b_par   = (const float*)d_in[10];
    const float* W_add   = (const float*)d_in[11];
    const float* b_add   = (const float*)d_in[12];
    float* out = (float*)d_out;

    static int smem_set = 0;
    if (!smem_set) {
        cudaFuncSetAttribute(gssm_mma_kernel,
                             cudaFuncAttributeMaxDynamicSharedMemorySize,
                             SMEM_BYTES);
        smem_set = 1;
    }

    // Prep: split/convert inputs
    xsplit_kernel<<<((size_t)B_ * T_ * DIN_) / (256 * 8), 256>>>(x);
    wtsplit_kernel<<<dim3(32, 16, 3), 256>>>(W_lam, W_delt, W_inp);
    xs_kernel<<<dim3(DIN_ / 128, B_), 128>>>(x);

    // Main fused tensor-core GEMM + scan-reduce
    gssm_mma_kernel<<<dim3(NMB, B_ * NTT2), 256, SMEM_BYTES>>>(b_lam, b_delt, b_inp);

    // Heads
    parity_kernel<<<B_, K_>>>(W_theta, b_theta, W_par, b_par, out);
    combine_kernel<<<B_, M_>>>(W_add, b_add, out);
}